// round 1
// baseline (speedup 1.0000x reference)
#include <cuda_runtime.h>
#include <cstdint>

#define D_    6
#define K_    16
#define CIN_  13
#define NL_   3
#define SLOPE_ 0.2f
#define EPS_   1e-5f

// Inputs per metadata order:
// 0: dist       [B,N,K,1]  float32   (B*N*K = 6,400,000)
// 1: atomtypes  [B,N,K,D]  float32   (38,400,000)
// 2: W1 [3,13,13]  3: b1 [3,13]  4: W2 [3,13,6]  5: b2 [3,6]  6: gw [3,6]  7: gb [3,6]
// Output: point_emb [B,N,D] float32

__global__ __launch_bounds__(128, 2)
void atom_mp_kernel(const float* __restrict__ dist,
                    const float* __restrict__ atom,
                    const float* __restrict__ W1,
                    const float* __restrict__ b1,
                    const float* __restrict__ W2,
                    const float* __restrict__ b2,
                    const float* __restrict__ gw,
                    const float* __restrict__ gb,
                    float* __restrict__ out,
                    int npts)
{
    // ---- stage all weights in shared memory (uniform access -> LDS broadcast) ----
    __shared__ float sW1[NL_ * CIN_ * CIN_];   // 507
    __shared__ float sb1[NL_ * CIN_];          // 39
    __shared__ float sW2[NL_ * CIN_ * D_];     // 234
    __shared__ float sb2[NL_ * D_];            // 18
    __shared__ float sgw[NL_ * D_];            // 18
    __shared__ float sgb[NL_ * D_];            // 18

    for (int i = threadIdx.x; i < NL_ * CIN_ * CIN_; i += blockDim.x) sW1[i] = W1[i];
    for (int i = threadIdx.x; i < NL_ * CIN_;        i += blockDim.x) sb1[i] = b1[i];
    for (int i = threadIdx.x; i < NL_ * CIN_ * D_;   i += blockDim.x) sW2[i] = W2[i];
    for (int i = threadIdx.x; i < NL_ * D_;          i += blockDim.x) {
        sb2[i] = b2[i]; sgw[i] = gw[i]; sgb[i] = gb[i];
    }
    __syncthreads();

    int p = blockIdx.x * blockDim.x + threadIdx.x;
    if (p >= npts) return;

    // ---- load this point's inputs once; keep register-resident across all layers ----
    float a[K_ * D_];   // 96 floats of atomtypes
    float dd[K_];       // 16 floats of dist

    {
        const float4* ap = reinterpret_cast<const float4*>(atom + (size_t)p * (K_ * D_));
        #pragma unroll
        for (int i = 0; i < (K_ * D_) / 4; i++) {
            float4 v = ap[i];
            a[4 * i + 0] = v.x; a[4 * i + 1] = v.y;
            a[4 * i + 2] = v.z; a[4 * i + 3] = v.w;
        }
        const float4* dp = reinterpret_cast<const float4*>(dist + (size_t)p * K_);
        #pragma unroll
        for (int i = 0; i < K_ / 4; i++) {
            float4 v = dp[i];
            dd[4 * i + 0] = v.x; dd[4 * i + 1] = v.y;
            dd[4 * i + 2] = v.z; dd[4 * i + 3] = v.w;
        }
    }

    float pe[D_];
    #pragma unroll
    for (int c = 0; c < D_; c++) pe[c] = 1.0f;

    for (int l = 0; l < NL_; l++) {
        const float* w1l = sW1 + l * CIN_ * CIN_;
        const float* b1l = sb1 + l * CIN_;
        const float* w2l = sW2 + l * CIN_ * D_;
        const float* b2l = sb2 + l * D_;
        const float* gwl = sgw + l * D_;
        const float* gbl = sgb + l * D_;

        // hsum[j] = sum_k lrelu( b1[j] + pemb@W1[0:6,j] + atom_k@W1[6:12,j] + dist_k*W1[12,j] )
        float hsum[CIN_];
        #pragma unroll
        for (int j = 0; j < CIN_; j++) {
            // column j of W1 in registers (13 LDS, hoisted above the k loop)
            float wj[CIN_];
            #pragma unroll
            for (int c = 0; c < CIN_; c++) wj[c] = w1l[c * CIN_ + j];

            float hb = b1l[j];
            #pragma unroll
            for (int d = 0; d < D_; d++) hb = fmaf(pe[d], wj[d], hb);

            // two accumulators to shorten the serial FADD chain over k
            float acc0 = 0.0f, acc1 = 0.0f;
            #pragma unroll
            for (int k = 0; k < K_; k++) {
                float h = hb;
                #pragma unroll
                for (int d = 0; d < D_; d++) h = fmaf(a[k * D_ + d], wj[D_ + d], h);
                h = fmaf(dd[k], wj[2 * D_], h);
                float lr = fmaxf(h, SLOPE_ * h);   // leaky relu
                if (k & 1) acc1 += lr; else acc0 += lr;
            }
            hsum[j] = acc0 + acc1;
        }

        // msg = hsum @ W2 + K*b2   (W2 GEMV hoisted out of the k loop)
        float msg[D_];
        #pragma unroll
        for (int i = 0; i < D_; i++) {
            float m = (float)K_ * b2l[i];
            #pragma unroll
            for (int j = 0; j < CIN_; j++) m = fmaf(hsum[j], w2l[j * D_ + i], m);
            msg[i] = m;
        }

        // GroupNorm(2 groups of 3) + affine + lrelu + residual
        #pragma unroll
        for (int g = 0; g < 2; g++) {
            float m0 = msg[3 * g + 0], m1 = msg[3 * g + 1], m2 = msg[3 * g + 2];
            float mu = (m0 + m1 + m2) * (1.0f / 3.0f);
            float e0 = m0 - mu, e1 = m1 - mu, e2 = m2 - mu;
            float var = (e0 * e0 + e1 * e1 + e2 * e2) * (1.0f / 3.0f);
            float rs = rsqrtf(var + EPS_);
            #pragma unroll
            for (int c = 0; c < 3; c++) {
                int ch = 3 * g + c;
                float xn = (msg[ch] - mu) * rs;
                float y  = fmaf(xn, gwl[ch], gbl[ch]);
                pe[ch] += fmaxf(y, SLOPE_ * y);
            }
        }
    }

    // ---- write point_emb ----
    float* op = out + (size_t)p * D_;
    #pragma unroll
    for (int c = 0; c < D_; c++) op[c] = pe[c];
}

extern "C" void kernel_launch(void* const* d_in, const int* in_sizes, int n_in,
                              void* d_out, int out_size)
{
    const float* dist = (const float*)d_in[0];
    const float* atom = (const float*)d_in[1];
    const float* W1   = (const float*)d_in[2];
    const float* b1   = (const float*)d_in[3];
    const float* W2   = (const float*)d_in[4];
    const float* b2   = (const float*)d_in[5];
    const float* gw   = (const float*)d_in[6];
    const float* gb   = (const float*)d_in[7];
    float* out = (float*)d_out;

    int npts = in_sizes[1] / (K_ * D_);   // B*N = 400000

    int block = 128;
    int grid = (npts + block - 1) / block;
    atom_mp_kernel<<<grid, block>>>(dist, atom, W1, b1, W2, b2, gw, gb, out, npts);
}

// round 4
// speedup vs baseline: 1.1785x; 1.1785x over previous
#include <cuda_runtime.h>
#include <cstdint>

#define D_    6
#define K_    16
#define CIN_  13
#define NL_   3
#define SLOPE_ 0.2f
#define EPS_   1e-5f

typedef unsigned long long u64;

// ---- packed f32x2 helpers (sm_103a: FFMA2 / FMUL2 on register pairs) ----
__device__ __forceinline__ u64 pk2(float lo, float hi) {
    u64 r; asm("mov.b64 %0, {%1, %2};" : "=l"(r) : "f"(lo), "f"(hi)); return r;
}
__device__ __forceinline__ void up2(u64 v, float& lo, float& hi) {
    asm("mov.b64 {%0, %1}, %2;" : "=f"(lo), "=f"(hi) : "l"(v));
}
__device__ __forceinline__ u64 fma2(u64 a, u64 b, u64 c) {
    u64 d; asm("fma.rn.f32x2 %0, %1, %2, %3;" : "=l"(d) : "l"(a), "l"(b), "l"(c)); return d;
}
__device__ __forceinline__ u64 mul2(u64 a, u64 b) {
    u64 d; asm("mul.rn.f32x2 %0, %1, %2;" : "=l"(d) : "l"(a), "l"(b)); return d;
}

// Inputs per metadata order:
// 0: dist [B,N,K,1] f32   1: atomtypes [B,N,K,D] f32
// 2: W1 [3,13,13]  3: b1 [3,13]  4: W2 [3,13,6]  5: b2 [3,6]  6: gw [3,6]  7: gb [3,6]
// Output: point_emb [B,N,D] f32

__global__ __launch_bounds__(128, 2)
void atom_mp_kernel(const float* __restrict__ dist,
                    const float* __restrict__ atom,
                    const float* __restrict__ W1,
                    const float* __restrict__ b1,
                    const float* __restrict__ W2,
                    const float* __restrict__ b2,
                    const float* __restrict__ gw,
                    const float* __restrict__ gb,
                    float* __restrict__ out,
                    int npts)
{
    // W1 stored TRANSPOSED and broadcast-packed: sW1p[l][j][c] = (w, w), w = W1[l][c][j].
    // W2 stored pair-packed:                     sW2p[l][j][i] = (W2[l][j][2i], W2[l][j][2i+1]).
    // All 64-bit shared data lives in natively 8-aligned u64 arrays — no reinterpret casts.
    __shared__ u64   sW1p[NL_ * CIN_ * CIN_];        // 507 * 8B
    __shared__ u64   sW2p[NL_ * CIN_ * (D_ / 2)];    // 117 * 8B
    __shared__ float sb1[NL_ * CIN_];
    __shared__ float sb2[NL_ * D_];
    __shared__ float sgw[NL_ * D_];
    __shared__ float sgb[NL_ * D_];

    for (int i = threadIdx.x; i < NL_ * CIN_ * CIN_; i += blockDim.x) {
        int l = i / (CIN_ * CIN_), r = i % (CIN_ * CIN_);
        int j = r / CIN_, c = r % CIN_;
        float w = W1[l * CIN_ * CIN_ + c * CIN_ + j];
        sW1p[i] = pk2(w, w);
    }
    for (int i = threadIdx.x; i < NL_ * CIN_ * (D_ / 2); i += blockDim.x) {
        int l = i / (CIN_ * (D_ / 2)), r = i % (CIN_ * (D_ / 2));
        int j = r / (D_ / 2), q = r % (D_ / 2);
        const float* src = W2 + (l * CIN_ + j) * D_ + 2 * q;
        sW2p[i] = pk2(src[0], src[1]);
    }
    for (int i = threadIdx.x; i < NL_ * CIN_; i += blockDim.x) sb1[i] = b1[i];
    for (int i = threadIdx.x; i < NL_ * D_;   i += blockDim.x) {
        sb2[i] = b2[i]; sgw[i] = gw[i]; sgb[i] = gb[i];
    }
    __syncthreads();

    int p = blockIdx.x * blockDim.x + threadIdx.x;
    if (p >= npts) return;

    // ---- load inputs once, pack neighbor pairs (2q, 2q+1) into f32x2 lanes ----
    float a[K_ * D_];
    {
        const float4* ap = reinterpret_cast<const float4*>(atom + (size_t)p * (K_ * D_));
        #pragma unroll
        for (int i = 0; i < (K_ * D_) / 4; i++) {
            float4 v = ap[i];
            a[4 * i + 0] = v.x; a[4 * i + 1] = v.y;
            a[4 * i + 2] = v.z; a[4 * i + 3] = v.w;
        }
    }
    u64 a2[(K_ / 2) * D_];
    #pragma unroll
    for (int q = 0; q < K_ / 2; q++)
        #pragma unroll
        for (int d = 0; d < D_; d++)
            a2[q * D_ + d] = pk2(a[(2 * q) * D_ + d], a[(2 * q + 1) * D_ + d]);

    u64 dd2[K_ / 2];
    {
        const float4* dp = reinterpret_cast<const float4*>(dist + (size_t)p * K_);
        #pragma unroll
        for (int i = 0; i < K_ / 4; i++) {
            float4 v = dp[i];
            dd2[2 * i + 0] = pk2(v.x, v.y);
            dd2[2 * i + 1] = pk2(v.z, v.w);
        }
    }

    const u64 slope2 = pk2(SLOPE_, SLOPE_);

    float pe[D_];
    #pragma unroll
    for (int c = 0; c < D_; c++) pe[c] = 1.0f;

    #pragma unroll 1   // keep per-layer body in I$; l stays a runtime index
    for (int l = 0; l < NL_; l++) {
        const u64*   w1l = sW1p + l * CIN_ * CIN_;
        const u64*   w2l = sW2p + l * CIN_ * (D_ / 2);
        const float* b1l = sb1 + l * CIN_;
        const float* b2l = sb2 + l * D_;
        const float* gwl = sgw + l * D_;
        const float* gbl = sgb + l * D_;

        float hsum[CIN_];
        #pragma unroll
        for (int j = 0; j < CIN_; j++) {
            // packed column j of W1^T: 13 x LDS.64, each already (w,w)
            u64 wj[CIN_];
            #pragma unroll
            for (int c = 0; c < CIN_; c++) wj[c] = w1l[j * CIN_ + c];

            // scalar part: bias + point_emb contribution (same for every neighbor)
            float hb = b1l[j];
            #pragma unroll
            for (int d = 0; d < D_; d++) {
                float wlo, whi; up2(wj[d], wlo, whi);   // lo half = w (reg view, no math)
                hb = fmaf(pe[d], wlo, hb);
            }
            u64 hb2 = pk2(hb, hb);

            float acc0 = 0.0f, acc1 = 0.0f;
            #pragma unroll
            for (int q = 0; q < K_ / 2; q++) {
                u64 h = hb2;
                #pragma unroll
                for (int d = 0; d < D_; d++)
                    h = fma2(a2[q * D_ + d], wj[D_ + d], h);
                h = fma2(dd2[q], wj[2 * D_], h);
                u64 s = mul2(h, slope2);
                float h0, h1, s0, s1;
                up2(h, h0, h1); up2(s, s0, s1);
                acc0 += fmaxf(h0, s0);       // leaky relu, two scalar FMNMX
                acc1 += fmaxf(h1, s1);
            }
            hsum[j] = acc0 + acc1;
        }

        // msg = hsum @ W2 + K*b2, packed over output-channel pairs (3 pairs of D=6)
        u64 msg2[D_ / 2];
        #pragma unroll
        for (int i = 0; i < D_ / 2; i++)
            msg2[i] = pk2((float)K_ * b2l[2 * i], (float)K_ * b2l[2 * i + 1]);
        #pragma unroll
        for (int j = 0; j < CIN_; j++) {
            u64 hj = pk2(hsum[j], hsum[j]);
            #pragma unroll
            for (int i = 0; i < D_ / 2; i++)
                msg2[i] = fma2(hj, w2l[j * (D_ / 2) + i], msg2[i]);
        }
        float msg[D_];
        #pragma unroll
        for (int i = 0; i < D_ / 2; i++) up2(msg2[i], msg[2 * i], msg[2 * i + 1]);

        // GroupNorm(2 groups of 3) + affine + lrelu + residual
        #pragma unroll
        for (int g = 0; g < 2; g++) {
            float m0 = msg[3 * g + 0], m1 = msg[3 * g + 1], m2 = msg[3 * g + 2];
            float mu = (m0 + m1 + m2) * (1.0f / 3.0f);
            float e0 = m0 - mu, e1 = m1 - mu, e2 = m2 - mu;
            float var = (e0 * e0 + e1 * e1 + e2 * e2) * (1.0f / 3.0f);
            float rs = rsqrtf(var + EPS_);
            #pragma unroll
            for (int c = 0; c < 3; c++) {
                int ch = 3 * g + c;
                float xn = (msg[ch] - mu) * rs;
                float y  = fmaf(xn, gwl[ch], gbl[ch]);
                pe[ch] += fmaxf(y, SLOPE_ * y);
            }
        }
    }

    // ---- write point_emb: rows are 24B, 24p % 8 == 0, d_out is allocation-aligned ----
    float2* op = reinterpret_cast<float2*>(out + (size_t)p * D_);
    #pragma unroll
    for (int i = 0; i < D_ / 2; i++) {
        float2 v; v.x = pe[2 * i]; v.y = pe[2 * i + 1];
        op[i] = v;
    }
}

extern "C" void kernel_launch(void* const* d_in, const int* in_sizes, int n_in,
                              void* d_out, int out_size)
{
    const float* dist = (const float*)d_in[0];
    const float* atom = (const float*)d_in[1];
    const float* W1   = (const float*)d_in[2];
    const float* b1   = (const float*)d_in[3];
    const float* W2   = (const float*)d_in[4];
    const float* b2   = (const float*)d_in[5];
    const float* gw   = (const float*)d_in[6];
    const float* gb   = (const float*)d_in[7];
    float* out = (float*)d_out;

    int npts = in_sizes[1] / (K_ * D_);   // B*N

    int block = 128;
    int grid = (npts + block - 1) / block;
    atom_mp_kernel<<<grid, block>>>(dist, atom, W1, b1, W2, b2, gw, gb, out, npts);
}